// round 10
// baseline (speedup 1.0000x reference)
#include <cuda_runtime.h>

// ---------------- constants ----------------
#define D0 65
#define DD 4225          // 65*65
#define DDD 274625       // 65*65*65
#define S 32
#define SSS 32768        // 32^3
#define NB 2
#define C2 32
#define CO 100
#define G 32             // sites per block in invconv
#define LIST_STRIDE 72000

// ---------------- static scratch ----------------
__device__ float g_h1[NB*C2*SSS];   // PLANAR [n][c][z][y][x]
__device__ float g_h2[NB*SSS*C2];   // channels-last [n][z][y][x][c]
__device__ float g_m1[NB*SSS];
__device__ float g_W2T[27*32*32];   // [tap][ci][co]
__device__ float g_WT[27*32*100];   // [tap][ci][co]
__device__ float g_a2[32], g_k2[32];
__device__ int   g_list[8*LIST_STRIDE];
__device__ int   g_cnt[8];

// ---------------- f32x2 helpers ----------------
__device__ __forceinline__ void ffma2(unsigned long long &d, unsigned long long a, unsigned long long b) {
    asm("fma.rn.f32x2 %0, %1, %2, %0;" : "+l"(d) : "l"(a), "l"(b));
}
__device__ __forceinline__ unsigned long long pack2(float x) {
    unsigned long long r;
    asm("mov.b64 %0, {%1, %1};" : "=l"(r) : "f"(x));
    return r;
}
__device__ __forceinline__ float2 unpack2(unsigned long long v) {
    float2 r;
    asm("mov.b64 {%0, %1}, %2;" : "=f"(r.x), "=f"(r.y) : "l"(v));
    return r;
}

// ---------------- prep: fold BN2, transpose weights, reset counters ----------------
__global__ void prep_kernel(const float* __restrict__ W2, const float* __restrict__ Winv,
                            const float* __restrict__ b2, const float* __restrict__ g2,
                            const float* __restrict__ bt2, const float* __restrict__ rm2,
                            const float* __restrict__ rv2) {
    int tid = blockIdx.x * blockDim.x + threadIdx.x;
    int nth = gridDim.x * blockDim.x;
    if (tid < 8) g_cnt[tid] = 0;
    if (tid < 32) {
        float a2 = g2[tid] * rsqrtf(rv2[tid] + 1e-5f);
        g_a2[tid] = a2;
        g_k2[tid] = (b2[tid] - rm2[tid]) * a2 + bt2[tid];
    }
    for (int i = tid; i < 27 * 32 * 32; i += nth) {
        int k = i / 1024, r = i % 1024, ci = r / 32, co = r % 32;
        g_W2T[i] = W2[(co * 32 + ci) * 27 + k];
    }
    for (int i = tid; i < 27 * 32 * 100; i += nth) {
        int k = i / 3200, r = i % 3200, ci = r / 100, co = r % 100;
        g_WT[i] = Winv[(co * 32 + ci) * 27 + k];
    }
}

// ---------------- conv1 + BN + ReLU + mask (self-contained BN fold) ----------------
__global__ void conv1_kernel(const float* __restrict__ x, const int* __restrict__ mask0,
                             const float* __restrict__ W1,
                             const float* __restrict__ b1, const float* __restrict__ g1,
                             const float* __restrict__ bt1, const float* __restrict__ rm1,
                             const float* __restrict__ rv1) {
    __shared__ float w1s[27 * 32];
    __shared__ float a1s[32], k1s[32];
    int tid = threadIdx.x;
    for (int i = tid; i < 864; i += 128) {
        int k = i >> 5, c = i & 31;
        w1s[i] = W1[c * 27 + k];
    }
    if (tid < 32) {
        float a = g1[tid] * rsqrtf(rv1[tid] + 1e-5f);
        a1s[tid] = a;
        k1s[tid] = (b1[tid] - rm1[tid]) * a + bt1[tid];
    }
    __syncthreads();

    int ox = tid & 31;
    int oy = blockIdx.x * 4 + (tid >> 5);
    int oz = blockIdx.y;
    int n  = blockIdx.z;

    float acc[32];
#pragma unroll
    for (int c = 0; c < 32; c++) acc[c] = 0.f;
    int cnt = 0;
    const float* xb = x + n * DDD;
    const int*   mb = mask0 + n * DDD;

    for (int kd = 0; kd < 3; kd++)
        for (int kh = 0; kh < 3; kh++) {
            int base = (2 * oz + kd) * DD + (2 * oy + kh) * D0 + 2 * ox;
#pragma unroll
            for (int kw = 0; kw < 3; kw++) {
                float v = xb[base + kw];
                cnt += mb[base + kw];
                const float* wq = &w1s[((kd * 3 + kh) * 3 + kw) * 32];
#pragma unroll
                for (int c = 0; c < 32; c++) acc[c] += v * wq[c];
            }
        }

    float m = (cnt > 0) ? 1.f : 0.f;
    int loc = (oz * S + oy) * S + ox;
    g_m1[n * SSS + loc] = m;
    float* hp = &g_h1[n * (C2 * SSS) + loc];
#pragma unroll
    for (int c = 0; c < 32; c++)
        hp[c * SSS] = fmaxf(acc[c] * a1s[c] + k1s[c], 0.f) * m;
}

// ---------------- build lists: block-aggregated atomics ----------------
__global__ void buildlist_kernel(const int* __restrict__ mask0) {
    __shared__ int lc[8], lb[8];
    int tid = threadIdx.x;
    int i = blockIdx.x * 256 + tid;
    if (tid < 8) lc[tid] = 0;
    __syncthreads();
    int cls = -1, myp = 0;
    if (i < NB * DDD && mask0[i]) {
        int r = i % DDD;
        int oz = r / DD;
        int r2 = r % DD;
        int oy = r2 / D0;
        int ox = r2 % D0;
        cls = ((oz & 1) << 2) | ((oy & 1) << 1) | (ox & 1);
        myp = atomicAdd(&lc[cls], 1);
    }
    __syncthreads();
    if (tid < 8 && lc[tid] > 0) lb[tid] = atomicAdd(&g_cnt[tid], lc[tid]);
    __syncthreads();
    if (cls >= 0) {
        int slot = cls * LIST_STRIDE + lb[cls] + myp;
        g_list[slot] = i;
    }
}

// ---------------- conv2: thread = (x-pair, co-half); smem weights; f32x2 ----------
// block = 256 threads: xh = tid&15, ch = (tid>>4)&1, yy = tid>>5 (8 y rows)
// grid = (4, 32, 2), dyn smem = 27*1024 floats (110.6 KB)
__global__ __launch_bounds__(256) void conv2_kernel() {
    extern __shared__ float w2s[];   // [tap][ci][co0..31]
    int tid = threadIdx.x;
    {
        const float4* src = (const float4*)g_W2T;
        float4* dst = (float4*)w2s;
        for (int i = tid; i < 27 * 32 * 8; i += 256) dst[i] = src[i];
    }
    __syncthreads();

    int xh = tid & 15;               // site pair ox0 = 2*xh, ox1 = 2*xh+1
    int ch = (tid >> 4) & 1;         // co-half: co = 16*ch .. 16*ch+15
    int oy = blockIdx.x * 8 + (tid >> 5);
    int oz = blockIdx.y;
    int n  = blockIdx.z;
    int cobase = ch * 16;

    unsigned long long accA[8], accB[8];   // 8 co-pairs per site
#pragma unroll
    for (int i = 0; i < 8; i++) { accA[i] = 0ull; accB[i] = 0ull; }

    const float* hbase = g_h1 + n * (C2 * SSS);
    int xm1 = 2 * xh - 1;
    bool x0ok = (xh != 0);
    bool x3ok = (xh != 15);

    for (int kd = 0; kd < 3; kd++) {
        int zs = oz + kd - 1;
        if ((unsigned)zs >= 32u) continue;
        for (int kh = 0; kh < 3; kh++) {
            int ys = oy + kh - 1;
            bool yok = (unsigned)ys < 32u;
            const float* rowp = hbase + zs * 1024 + ys * 32 + xm1;
            int tap0 = (kd * 3 + kh) * 3;
            const float* wt0 = &w2s[(tap0 + 0) * 1024 + cobase];
            const float* wt1 = &w2s[(tap0 + 1) * 1024 + cobase];
            const float* wt2 = &w2s[(tap0 + 2) * 1024 + cobase];
#pragma unroll 4
            for (int ci = 0; ci < 32; ci++) {
                const float* rp = rowp + ci * SSS;
                float h0 = (yok && x0ok) ? rp[0] : 0.f;
                float h1v = yok ? rp[1] : 0.f;
                float h2v = yok ? rp[2] : 0.f;
                float h3 = (yok && x3ok) ? rp[3] : 0.f;
                unsigned long long hh0 = pack2(h0);
                unsigned long long hh1 = pack2(h1v);
                unsigned long long hh2 = pack2(h2v);
                unsigned long long hh3 = pack2(h3);
                const ulonglong2* wq0 = (const ulonglong2*)(wt0 + ci * 32);
                const ulonglong2* wq1 = (const ulonglong2*)(wt1 + ci * 32);
                const ulonglong2* wq2 = (const ulonglong2*)(wt2 + ci * 32);
#pragma unroll
                for (int q = 0; q < 4; q++) {
                    ulonglong2 w0 = wq0[q];
                    ulonglong2 w1 = wq1[q];
                    ulonglong2 w2 = wq2[q];
                    // site0 uses h[j=kw], site1 uses h[j=kw+1]
                    ffma2(accA[2 * q],     w0.x, hh0);
                    ffma2(accA[2 * q + 1], w0.y, hh0);
                    ffma2(accB[2 * q],     w0.x, hh1);
                    ffma2(accB[2 * q + 1], w0.y, hh1);
                    ffma2(accA[2 * q],     w1.x, hh1);
                    ffma2(accA[2 * q + 1], w1.y, hh1);
                    ffma2(accB[2 * q],     w1.x, hh2);
                    ffma2(accB[2 * q + 1], w1.y, hh2);
                    ffma2(accA[2 * q],     w2.x, hh2);
                    ffma2(accA[2 * q + 1], w2.y, hh2);
                    ffma2(accB[2 * q],     w2.x, hh3);
                    ffma2(accB[2 * q + 1], w2.y, hh3);
                }
            }
        }
    }

    int loc0 = (oz * S + oy) * S + 2 * xh;
    float m0 = g_m1[n * SSS + loc0];
    float m1v = g_m1[n * SSS + loc0 + 1];
    float* op0 = &g_h2[(n * SSS + loc0) * 32 + cobase];
    float* op1 = op0 + 32;
#pragma unroll
    for (int j = 0; j < 8; j++) {
        float2 va = unpack2(accA[j]);
        float2 vb = unpack2(accB[j]);
        int c0 = cobase + 2 * j, c1 = c0 + 1;
        float a0 = g_a2[c0], a1 = g_a2[c1], k0 = g_k2[c0], k1 = g_k2[c1];
        op0[2 * j]     = fmaxf(va.x * a0 + k0, 0.f) * m0;
        op0[2 * j + 1] = fmaxf(va.y * a1 + k1, 0.f) * m0;
        op1[2 * j]     = fmaxf(vb.x * a0 + k0, 0.f) * m1v;
        op1[2 * j + 1] = fmaxf(vb.y * a1 + k1, 0.f) * m1v;
    }
}

// ---------------- zero-fill output ----------------
__global__ void zero_kernel(float4* __restrict__ out4, int n4, float* __restrict__ out, int rem_start, int total) {
    int i = blockIdx.x * blockDim.x + threadIdx.x;
    if (i < n4) out4[i] = make_float4(0.f, 0.f, 0.f, 0.f);
    if (i == 0) {
        for (int j = rem_start; j < total; j++) out[j] = 0.f;
    }
}

// ---------------- inverse (transposed stride-2) conv at active sites, f32x2 ----------
// grid = (2250, 8): blockIdx.y = parity class; 128 threads (co = tid)
__global__ __launch_bounds__(128) void invconv_kernel(const float* __restrict__ binv,
                                                      float* __restrict__ out) {
    int cls = blockIdx.y;
    int count = g_cnt[cls];
    int base = blockIdx.x * G;
    if (base >= count) return;

    int pz = (cls >> 2) & 1, py = (cls >> 1) & 1, px = cls & 1;
    int ndz = pz ? 1 : 2, ndy = py ? 1 : 2, ndx = px ? 1 : 2;
    int numT = ndz * ndy * ndx;

    __shared__ float h2s[8 * 32 * 36];   // [t][ci][pad36] g fastest
    __shared__ int   sbase[G * 8];
    __shared__ int   kmap[8];
    __shared__ int   ssite[G];
    __shared__ int   sout[G];

    int tid = threadIdx.x;
    int ng = count - base;
    if (ng > G) ng = G;

    if (tid < ng) {
        int s = g_list[cls * LIST_STRIDE + base + tid];
        ssite[tid] = s;
        sout[tid] = s + ((s >= DDD) ? 99 * DDD : 0);   // n*CO*DDD + r (co added later)
    }
    if (tid < numT) {
        int t = tid;
        int tz = t / (ndy * ndx), ty = (t / ndx) % ndy, tx = t % ndx;
        int kd = pz ? 1 : tz * 2, kh = py ? 1 : ty * 2, kw = px ? 1 : tx * 2;
        kmap[t] = (kd * 3 + kh) * 3 + kw;
    }
    __syncthreads();

    for (int i = tid; i < ng * numT; i += 128) {
        int g = i / numT, t = i % numT;
        int s = ssite[g];
        int n = s / DDD;
        int r = s % DDD;
        int oz = r / DD;
        int r2 = r % DD;
        int oy = r2 / D0;
        int ox = r2 % D0;
        int tz = t / (ndy * ndx), ty = (t / ndx) % ndy, tx = t % ndx;
        int kd = pz ? 1 : tz * 2, kh = py ? 1 : ty * 2, kw = px ? 1 : tx * 2;
        int iz = (oz + kd - 2) >> 1;
        int iy = (oy + kh - 2) >> 1;
        int ix = (ox + kw - 2) >> 1;
        bool v = ((unsigned)iz < 32u) && ((unsigned)iy < 32u) && ((unsigned)ix < 32u);
        sbase[g * 8 + t] = v ? ((((n * S + iz) * S + iy) * S + ix) * 32) : -1;
    }
    __syncthreads();

    // cooperative load of h2 tap rows (source ci-coalesced, dest [t][ci][g])
    for (int i = tid; i < G * numT * 32; i += 128) {
        int ci = i & 31;
        int gt = i >> 5;
        int g = gt / numT, t = gt % numT;
        int b = (g < ng) ? sbase[g * 8 + t] : -1;
        h2s[(t * 32 + ci) * 36 + g] = (b >= 0) ? g_h2[b + ci] : 0.f;
    }
    __syncthreads();

    int co = tid;
    bool cok = (co < CO);
    float bv = cok ? __ldg(&binv[co]) : 0.f;
    unsigned long long acc2[16];
    unsigned long long bb = pack2(bv);
#pragma unroll
    for (int j = 0; j < 16; j++) acc2[j] = bb;

    for (int t = 0; t < numT; t++) {
        const float* wp = g_WT + kmap[t] * 3200 + co;
        const float* hb = &h2s[(t * 32) * 36];
#pragma unroll 4
        for (int ci = 0; ci < 32; ci++) {
            float w = cok ? __ldg(wp + ci * 100) : 0.f;
            unsigned long long ww = pack2(w);
            const ulonglong2* hq = (const ulonglong2*)(hb + ci * 36);
#pragma unroll
            for (int q = 0; q < 8; q++) {
                ulonglong2 hv = hq[q];
                ffma2(acc2[2 * q],     ww, hv.x);
                ffma2(acc2[2 * q + 1], ww, hv.y);
            }
        }
    }

    if (cok) {
        int cd = co * DDD;
#pragma unroll
        for (int j = 0; j < 16; j++) {
            float2 v = unpack2(acc2[j]);
            int g0 = 2 * j, g1 = 2 * j + 1;
            if (g0 < ng) out[sout[g0] + cd] = v.x;
            if (g1 < ng) out[sout[g1] + cd] = v.y;
        }
    }
}

// ---------------- host-side stream/event resources (created once; host-only) -------
struct AuxRes {
    cudaStream_t s2;
    cudaEvent_t  eFork, eJoin;
    AuxRes() {
        cudaStreamCreateWithFlags(&s2, cudaStreamNonBlocking);
        cudaEventCreateWithFlags(&eFork, cudaEventDisableTiming);
        cudaEventCreateWithFlags(&eJoin, cudaEventDisableTiming);
    }
};

// ---------------- launch ----------------
extern "C" void kernel_launch(void* const* d_in, const int* in_sizes, int n_in,
                              void* d_out, int out_size) {
    const float* x    = (const float*)d_in[0];
    const int*   mask0 = (const int*)d_in[1];
    const float* W1   = (const float*)d_in[2];
    const float* b1   = (const float*)d_in[3];
    const float* g1   = (const float*)d_in[4];
    const float* bt1  = (const float*)d_in[5];
    const float* rm1  = (const float*)d_in[6];
    const float* rv1  = (const float*)d_in[7];
    const float* W2   = (const float*)d_in[8];
    const float* b2   = (const float*)d_in[9];
    const float* g2   = (const float*)d_in[10];
    const float* bt2  = (const float*)d_in[11];
    const float* rm2  = (const float*)d_in[12];
    const float* rv2  = (const float*)d_in[13];
    const float* Winv = (const float*)d_in[14];
    const float* binv = (const float*)d_in[15];
    float* out = (float*)d_out;

    static AuxRes R;   // host-only resources, created once

    cudaFuncSetAttribute(conv2_kernel, cudaFuncAttributeMaxDynamicSharedMemorySize,
                         27 * 32 * 32 * (int)sizeof(float));

    // main stream: prep -> conv1 -> conv2 -> (join) -> invconv
    prep_kernel<<<512, 256>>>(W2, Winv, b2, g2, bt2, rm2, rv2);

    // fork side stream after prep (buildlist needs g_cnt reset by prep)
    cudaEventRecord(R.eFork, 0);
    cudaStreamWaitEvent(R.s2, R.eFork, 0);
    buildlist_kernel<<<(NB * DDD + 255) / 256, 256, 0, R.s2>>>(mask0);
    int n4 = out_size >> 2;
    zero_kernel<<<(n4 + 255) / 256, 256, 0, R.s2>>>((float4*)d_out, n4, out, n4 << 2, out_size);
    cudaEventRecord(R.eJoin, R.s2);

    conv1_kernel<<<dim3(8, 32, 2), 128>>>(x, mask0, W1, b1, g1, bt1, rm1, rv1);
    conv2_kernel<<<dim3(4, 32, 2), 256, 27 * 32 * 32 * sizeof(float)>>>();

    // join: invconv needs buildlist + zero + conv2
    cudaStreamWaitEvent(0, R.eJoin, 0);
    invconv_kernel<<<dim3((LIST_STRIDE + G - 1) / G, 8), 128>>>(binv, out);
}

// round 11
// speedup vs baseline: 1.0413x; 1.0413x over previous
#include <cuda_runtime.h>

// ---------------- constants ----------------
#define D0 65
#define DD 4225          // 65*65
#define DDD 274625       // 65*65*65
#define S 32
#define SSS 32768        // 32^3
#define NB 2
#define C2 32
#define CO 100
#define G 32             // sites per block in invconv
#define LIST_STRIDE 72000

// ---------------- static scratch ----------------
__device__ float g_h1[NB*C2*SSS];   // PLANAR [n][c][z][y][x]
__device__ float g_h2[NB*SSS*C2];   // channels-last [n][z][y][x][c]
__device__ float g_m1[NB*SSS];
__device__ float g_W2T[27*32*32];   // [tap][ci][co]
__device__ float g_WT[27*32*100];   // [tap][ci][co]
__device__ float g_a2[32], g_k2[32];
__device__ int   g_list[8*LIST_STRIDE];
__device__ int   g_cnt[8];

// ---------------- f32x2 helpers ----------------
__device__ __forceinline__ void ffma2(unsigned long long &d, unsigned long long a, unsigned long long b) {
    asm("fma.rn.f32x2 %0, %1, %2, %0;" : "+l"(d) : "l"(a), "l"(b));
}
__device__ __forceinline__ unsigned long long pack2(float x) {
    unsigned long long r;
    asm("mov.b64 %0, {%1, %1};" : "=l"(r) : "f"(x));
    return r;
}
__device__ __forceinline__ float2 unpack2(unsigned long long v) {
    float2 r;
    asm("mov.b64 {%0, %1}, %2;" : "=f"(r.x), "=f"(r.y) : "l"(v));
    return r;
}

// ---------------- prep: fold BN2, transpose weights, reset counters ----------------
__global__ void prep_kernel(const float* __restrict__ W2, const float* __restrict__ Winv,
                            const float* __restrict__ b2, const float* __restrict__ g2,
                            const float* __restrict__ bt2, const float* __restrict__ rm2,
                            const float* __restrict__ rv2) {
    int tid = blockIdx.x * blockDim.x + threadIdx.x;
    int nth = gridDim.x * blockDim.x;
    if (tid < 8) g_cnt[tid] = 0;
    if (tid < 32) {
        float a2 = g2[tid] * rsqrtf(rv2[tid] + 1e-5f);
        g_a2[tid] = a2;
        g_k2[tid] = (b2[tid] - rm2[tid]) * a2 + bt2[tid];
    }
    for (int i = tid; i < 27 * 32 * 32; i += nth) {
        int k = i / 1024, r = i % 1024, ci = r / 32, co = r % 32;
        g_W2T[i] = W2[(co * 32 + ci) * 27 + k];
    }
    for (int i = tid; i < 27 * 32 * 100; i += nth) {
        int k = i / 3200, r = i % 3200, ci = r / 100, co = r % 100;
        g_WT[i] = Winv[(co * 32 + ci) * 27 + k];
    }
}

// ---------------- conv1 + BN + ReLU + mask (self-contained BN fold) ----------------
__global__ void conv1_kernel(const float* __restrict__ x, const int* __restrict__ mask0,
                             const float* __restrict__ W1,
                             const float* __restrict__ b1, const float* __restrict__ g1,
                             const float* __restrict__ bt1, const float* __restrict__ rm1,
                             const float* __restrict__ rv1) {
    __shared__ float w1s[27 * 32];
    __shared__ float a1s[32], k1s[32];
    int tid = threadIdx.x;
    for (int i = tid; i < 864; i += 128) {
        int k = i >> 5, c = i & 31;
        w1s[i] = W1[c * 27 + k];
    }
    if (tid < 32) {
        float a = g1[tid] * rsqrtf(rv1[tid] + 1e-5f);
        a1s[tid] = a;
        k1s[tid] = (b1[tid] - rm1[tid]) * a + bt1[tid];
    }
    __syncthreads();

    int ox = tid & 31;
    int oy = blockIdx.x * 4 + (tid >> 5);
    int oz = blockIdx.y;
    int n  = blockIdx.z;

    float acc[32];
#pragma unroll
    for (int c = 0; c < 32; c++) acc[c] = 0.f;
    int cnt = 0;
    const float* xb = x + n * DDD;
    const int*   mb = mask0 + n * DDD;

    for (int kd = 0; kd < 3; kd++)
        for (int kh = 0; kh < 3; kh++) {
            int base = (2 * oz + kd) * DD + (2 * oy + kh) * D0 + 2 * ox;
#pragma unroll
            for (int kw = 0; kw < 3; kw++) {
                float v = xb[base + kw];
                cnt += mb[base + kw];
                const float* wq = &w1s[((kd * 3 + kh) * 3 + kw) * 32];
#pragma unroll
                for (int c = 0; c < 32; c++) acc[c] += v * wq[c];
            }
        }

    float m = (cnt > 0) ? 1.f : 0.f;
    int loc = (oz * S + oy) * S + ox;
    g_m1[n * SSS + loc] = m;
    float* hp = &g_h1[n * (C2 * SSS) + loc];
#pragma unroll
    for (int c = 0; c < 32; c++)
        hp[c * SSS] = fmaxf(acc[c] * a1s[c] + k1s[c], 0.f) * m;
}

// ---------------- build lists: block-aggregated atomics ----------------
__global__ void buildlist_kernel(const int* __restrict__ mask0) {
    __shared__ int lc[8], lb[8];
    int tid = threadIdx.x;
    int i = blockIdx.x * 256 + tid;
    if (tid < 8) lc[tid] = 0;
    __syncthreads();
    int cls = -1, myp = 0;
    if (i < NB * DDD && mask0[i]) {
        int r = i % DDD;
        int oz = r / DD;
        int r2 = r % DD;
        int oy = r2 / D0;
        int ox = r2 % D0;
        cls = ((oz & 1) << 2) | ((oy & 1) << 1) | (ox & 1);
        myp = atomicAdd(&lc[cls], 1);
    }
    __syncthreads();
    if (tid < 8 && lc[tid] > 0) lb[tid] = atomicAdd(&g_cnt[tid], lc[tid]);
    __syncthreads();
    if (cls >= 0) {
        int slot = cls * LIST_STRIDE + lb[cls] + myp;
        g_list[slot] = i;
    }
}

// ---------------- conv2: block = (y8, oz, n, co-half); thread = (x-pair, co-quarter)
// block 256 threads: xh = tid&15, cq = (tid>>4)&1, yy = tid>>5
// grid = (8, 32, 2): blockIdx.x = (oyBase<<1)|ch ; dyn smem = 27*32*16 floats (55.3 KB)
__global__ __launch_bounds__(256) void conv2_kernel() {
    extern __shared__ float w2s[];   // [tap][ci][co 16 for this half]
    int tid = threadIdx.x;
    int ch = blockIdx.x & 1;
    {
        // copy this half's weights: for each (tap,ci): float4 j=0..3 of [ch*16..+16)
        const float4* src = (const float4*)g_W2T;
        float4* dst = (float4*)w2s;
        for (int i = tid; i < 27 * 32 * 4; i += 256) {
            int tc = i >> 2, j = i & 3;
            dst[tc * 4 + j] = src[tc * 8 + ch * 4 + j];
        }
    }
    __syncthreads();

    int xh = tid & 15;               // site pair ox0 = 2*xh, ox1 = 2*xh+1
    int cq = (tid >> 4) & 1;         // quarter within half: 8 co
    int oy = (blockIdx.x >> 1) * 8 + (tid >> 5);
    int oz = blockIdx.y;
    int n  = blockIdx.z;
    int cob = cq * 8;                // offset within the 16-wide smem slab
    int cobase = ch * 16 + cob;      // global co base (8 channels)

    unsigned long long accA[4], accB[4];   // 4 co-pairs per site
#pragma unroll
    for (int i = 0; i < 4; i++) { accA[i] = 0ull; accB[i] = 0ull; }

    const float* hbase = g_h1 + n * (C2 * SSS);
    int xm1 = 2 * xh - 1;
    bool x0ok = (xh != 0);
    bool x3ok = (xh != 15);

    for (int kd = 0; kd < 3; kd++) {
        int zs = oz + kd - 1;
        if ((unsigned)zs >= 32u) continue;
        for (int kh = 0; kh < 3; kh++) {
            int ys = oy + kh - 1;
            bool yok = (unsigned)ys < 32u;
            const float* rowp = hbase + zs * 1024 + ys * 32 + xm1;
            int tap0 = (kd * 3 + kh) * 3;
            const float* wt0 = &w2s[(tap0 + 0) * 512 + cob];
            const float* wt1 = &w2s[(tap0 + 1) * 512 + cob];
            const float* wt2 = &w2s[(tap0 + 2) * 512 + cob];
#pragma unroll 4
            for (int ci = 0; ci < 32; ci++) {
                const float* rp = rowp + ci * SSS;
                float h0 = (yok && x0ok) ? rp[0] : 0.f;
                float h1v = yok ? rp[1] : 0.f;
                float h2v = yok ? rp[2] : 0.f;
                float h3 = (yok && x3ok) ? rp[3] : 0.f;
                unsigned long long hh0 = pack2(h0);
                unsigned long long hh1 = pack2(h1v);
                unsigned long long hh2 = pack2(h2v);
                unsigned long long hh3 = pack2(h3);
                const ulonglong2* wq0 = (const ulonglong2*)(wt0 + ci * 16);
                const ulonglong2* wq1 = (const ulonglong2*)(wt1 + ci * 16);
                const ulonglong2* wq2 = (const ulonglong2*)(wt2 + ci * 16);
#pragma unroll
                for (int q = 0; q < 2; q++) {
                    ulonglong2 w0 = wq0[q];
                    ulonglong2 w1 = wq1[q];
                    ulonglong2 w2 = wq2[q];
                    // site0 uses h[j=kw], site1 uses h[j=kw+1]
                    ffma2(accA[2 * q],     w0.x, hh0);
                    ffma2(accA[2 * q + 1], w0.y, hh0);
                    ffma2(accB[2 * q],     w0.x, hh1);
                    ffma2(accB[2 * q + 1], w0.y, hh1);
                    ffma2(accA[2 * q],     w1.x, hh1);
                    ffma2(accA[2 * q + 1], w1.y, hh1);
                    ffma2(accB[2 * q],     w1.x, hh2);
                    ffma2(accB[2 * q + 1], w1.y, hh2);
                    ffma2(accA[2 * q],     w2.x, hh2);
                    ffma2(accA[2 * q + 1], w2.y, hh2);
                    ffma2(accB[2 * q],     w2.x, hh3);
                    ffma2(accB[2 * q + 1], w2.y, hh3);
                }
            }
        }
    }

    int loc0 = (oz * S + oy) * S + 2 * xh;
    float m0 = g_m1[n * SSS + loc0];
    float m1v = g_m1[n * SSS + loc0 + 1];
    float* op0 = &g_h2[(n * SSS + loc0) * 32 + cobase];
    float* op1 = op0 + 32;
#pragma unroll
    for (int j = 0; j < 4; j++) {
        float2 va = unpack2(accA[j]);
        float2 vb = unpack2(accB[j]);
        int c0 = cobase + 2 * j, c1 = c0 + 1;
        float a0 = g_a2[c0], a1 = g_a2[c1], k0 = g_k2[c0], k1 = g_k2[c1];
        op0[2 * j]     = fmaxf(va.x * a0 + k0, 0.f) * m0;
        op0[2 * j + 1] = fmaxf(va.y * a1 + k1, 0.f) * m0;
        op1[2 * j]     = fmaxf(vb.x * a0 + k0, 0.f) * m1v;
        op1[2 * j + 1] = fmaxf(vb.y * a1 + k1, 0.f) * m1v;
    }
}

// ---------------- zero-fill output ----------------
__global__ void zero_kernel(float4* __restrict__ out4, int n4, float* __restrict__ out, int rem_start, int total) {
    int i = blockIdx.x * blockDim.x + threadIdx.x;
    if (i < n4) out4[i] = make_float4(0.f, 0.f, 0.f, 0.f);
    if (i == 0) {
        for (int j = rem_start; j < total; j++) out[j] = 0.f;
    }
}

// ---------------- inverse (transposed stride-2) conv at active sites, f32x2 ----------
// grid = (2250, 8): blockIdx.y = parity class; 128 threads (co = tid)
__global__ __launch_bounds__(128) void invconv_kernel(const float* __restrict__ binv,
                                                      float* __restrict__ out) {
    int cls = blockIdx.y;
    int count = g_cnt[cls];
    int base = blockIdx.x * G;
    if (base >= count) return;

    int pz = (cls >> 2) & 1, py = (cls >> 1) & 1, px = cls & 1;
    int ndz = pz ? 1 : 2, ndy = py ? 1 : 2, ndx = px ? 1 : 2;
    int numT = ndz * ndy * ndx;

    __shared__ float h2s[8 * 32 * 36];   // [t][ci][pad36] g fastest
    __shared__ int   sbase[G * 8];
    __shared__ int   kmap[8];
    __shared__ int   ssite[G];
    __shared__ int   sout[G];

    int tid = threadIdx.x;
    int ng = count - base;
    if (ng > G) ng = G;

    if (tid < ng) {
        int s = g_list[cls * LIST_STRIDE + base + tid];
        ssite[tid] = s;
        sout[tid] = s + ((s >= DDD) ? 99 * DDD : 0);   // n*CO*DDD + r (co added later)
    }
    if (tid < numT) {
        int t = tid;
        int tz = t / (ndy * ndx), ty = (t / ndx) % ndy, tx = t % ndx;
        int kd = pz ? 1 : tz * 2, kh = py ? 1 : ty * 2, kw = px ? 1 : tx * 2;
        kmap[t] = (kd * 3 + kh) * 3 + kw;
    }
    __syncthreads();

    for (int i = tid; i < ng * numT; i += 128) {
        int g = i / numT, t = i % numT;
        int s = ssite[g];
        int n = s / DDD;
        int r = s % DDD;
        int oz = r / DD;
        int r2 = r % DD;
        int oy = r2 / D0;
        int ox = r2 % D0;
        int tz = t / (ndy * ndx), ty = (t / ndx) % ndy, tx = t % ndx;
        int kd = pz ? 1 : tz * 2, kh = py ? 1 : ty * 2, kw = px ? 1 : tx * 2;
        int iz = (oz + kd - 2) >> 1;
        int iy = (oy + kh - 2) >> 1;
        int ix = (ox + kw - 2) >> 1;
        bool v = ((unsigned)iz < 32u) && ((unsigned)iy < 32u) && ((unsigned)ix < 32u);
        sbase[g * 8 + t] = v ? ((((n * S + iz) * S + iy) * S + ix) * 32) : -1;
    }
    __syncthreads();

    // cooperative load of h2 tap rows (source ci-coalesced, dest [t][ci][g])
    for (int i = tid; i < G * numT * 32; i += 128) {
        int ci = i & 31;
        int gt = i >> 5;
        int g = gt / numT, t = gt % numT;
        int b = (g < ng) ? sbase[g * 8 + t] : -1;
        h2s[(t * 32 + ci) * 36 + g] = (b >= 0) ? g_h2[b + ci] : 0.f;
    }
    __syncthreads();

    int co = tid;
    bool cok = (co < CO);
    float bv = cok ? __ldg(&binv[co]) : 0.f;
    unsigned long long acc2[16];
    unsigned long long bb = pack2(bv);
#pragma unroll
    for (int j = 0; j < 16; j++) acc2[j] = bb;

    for (int t = 0; t < numT; t++) {
        const float* wp = g_WT + kmap[t] * 3200 + co;
        const float* hb = &h2s[(t * 32) * 36];
#pragma unroll 4
        for (int ci = 0; ci < 32; ci++) {
            float w = cok ? __ldg(wp + ci * 100) : 0.f;
            unsigned long long ww = pack2(w);
            const ulonglong2* hq = (const ulonglong2*)(hb + ci * 36);
#pragma unroll
            for (int q = 0; q < 8; q++) {
                ulonglong2 hv = hq[q];
                ffma2(acc2[2 * q],     ww, hv.x);
                ffma2(acc2[2 * q + 1], ww, hv.y);
            }
        }
    }

    if (cok) {
        int cd = co * DDD;
#pragma unroll
        for (int j = 0; j < 16; j++) {
            float2 v = unpack2(acc2[j]);
            int g0 = 2 * j, g1 = 2 * j + 1;
            if (g0 < ng) out[sout[g0] + cd] = v.x;
            if (g1 < ng) out[sout[g1] + cd] = v.y;
        }
    }
}

// ---------------- launch ----------------
extern "C" void kernel_launch(void* const* d_in, const int* in_sizes, int n_in,
                              void* d_out, int out_size) {
    const float* x    = (const float*)d_in[0];
    const int*   mask0 = (const int*)d_in[1];
    const float* W1   = (const float*)d_in[2];
    const float* b1   = (const float*)d_in[3];
    const float* g1   = (const float*)d_in[4];
    const float* bt1  = (const float*)d_in[5];
    const float* rm1  = (const float*)d_in[6];
    const float* rv1  = (const float*)d_in[7];
    const float* W2   = (const float*)d_in[8];
    const float* b2   = (const float*)d_in[9];
    const float* g2   = (const float*)d_in[10];
    const float* bt2  = (const float*)d_in[11];
    const float* rm2  = (const float*)d_in[12];
    const float* rv2  = (const float*)d_in[13];
    const float* Winv = (const float*)d_in[14];
    const float* binv = (const float*)d_in[15];
    float* out = (float*)d_out;

    cudaFuncSetAttribute(conv2_kernel, cudaFuncAttributeMaxDynamicSharedMemorySize,
                         27 * 32 * 16 * (int)sizeof(float));

    prep_kernel<<<512, 256>>>(W2, Winv, b2, g2, bt2, rm2, rv2);
    conv1_kernel<<<dim3(8, 32, 2), 128>>>(x, mask0, W1, b1, g1, bt1, rm1, rv1);
    buildlist_kernel<<<(NB * DDD + 255) / 256, 256>>>(mask0);
    conv2_kernel<<<dim3(8, 32, 2), 256, 27 * 32 * 16 * sizeof(float)>>>();

    int n4 = out_size >> 2;
    zero_kernel<<<(n4 + 255) / 256, 256>>>((float4*)d_out, n4, out, n4 << 2, out_size);

    invconv_kernel<<<dim3((LIST_STRIDE + G - 1) / G, 8), 128>>>(binv, out);
}

// round 12
// speedup vs baseline: 1.0589x; 1.0169x over previous
#include <cuda_runtime.h>

// ---------------- constants ----------------
#define D0 65
#define DD 4225          // 65*65
#define DDD 274625       // 65*65*65
#define S 32
#define SSS 32768        // 32^3
#define NB 2
#define C2 32
#define CO 100
#define G 32             // sites per block in invconv
#define LIST_STRIDE 72000
// padded h1 dims (1-voxel zero halo)
#define PX 34
#define PY 34
#define PROW 34          // x stride = 1, y stride = 34
#define PSLAB 1156       // 34*34
#define PVOL 39304       // 34*34*34

// ---------------- static scratch ----------------
__device__ float g_h1[NB*C2*PVOL];  // PLANAR PADDED [n][c][z+1][y+1][x+1]; halo stays 0
__device__ float g_h2[NB*SSS*C2];   // channels-last [n][z][y][x][c]
__device__ float g_m1[NB*SSS];
__device__ float g_W2T[27*32*32];   // [tap][ci][co]
__device__ float g_WT[27*32*100];   // [tap][ci][co]
__device__ float g_a2[32], g_k2[32];
__device__ int   g_list[8*LIST_STRIDE];
__device__ int   g_cnt[8];

// ---------------- f32x2 helpers ----------------
__device__ __forceinline__ void ffma2(unsigned long long &d, unsigned long long a, unsigned long long b) {
    asm("fma.rn.f32x2 %0, %1, %2, %0;" : "+l"(d) : "l"(a), "l"(b));
}
__device__ __forceinline__ unsigned long long pack2(float x) {
    unsigned long long r;
    asm("mov.b64 %0, {%1, %1};" : "=l"(r) : "f"(x));
    return r;
}
__device__ __forceinline__ float2 unpack2(unsigned long long v) {
    float2 r;
    asm("mov.b64 {%0, %1}, %2;" : "=f"(r.x), "=f"(r.y) : "l"(v));
    return r;
}

// ---------------- prep: fold BN2, transpose weights, reset counters ----------------
__global__ void prep_kernel(const float* __restrict__ W2, const float* __restrict__ Winv,
                            const float* __restrict__ b2, const float* __restrict__ g2,
                            const float* __restrict__ bt2, const float* __restrict__ rm2,
                            const float* __restrict__ rv2) {
    int tid = blockIdx.x * blockDim.x + threadIdx.x;
    int nth = gridDim.x * blockDim.x;
    if (tid < 8) g_cnt[tid] = 0;
    if (tid < 32) {
        float a2 = g2[tid] * rsqrtf(rv2[tid] + 1e-5f);
        g_a2[tid] = a2;
        g_k2[tid] = (b2[tid] - rm2[tid]) * a2 + bt2[tid];
    }
    for (int i = tid; i < 27 * 32 * 32; i += nth) {
        int k = i / 1024, r = i % 1024, ci = r / 32, co = r % 32;
        g_W2T[i] = W2[(co * 32 + ci) * 27 + k];
    }
    for (int i = tid; i < 27 * 32 * 100; i += nth) {
        int k = i / 3200, r = i % 3200, ci = r / 100, co = r % 100;
        g_WT[i] = Winv[(co * 32 + ci) * 27 + k];
    }
}

// ---------------- conv1 + BN + ReLU + mask (writes PADDED planar h1) ----------------
__global__ void conv1_kernel(const float* __restrict__ x, const int* __restrict__ mask0,
                             const float* __restrict__ W1,
                             const float* __restrict__ b1, const float* __restrict__ g1,
                             const float* __restrict__ bt1, const float* __restrict__ rm1,
                             const float* __restrict__ rv1) {
    __shared__ float w1s[27 * 32];
    __shared__ float a1s[32], k1s[32];
    int tid = threadIdx.x;
    for (int i = tid; i < 864; i += 128) {
        int k = i >> 5, c = i & 31;
        w1s[i] = W1[c * 27 + k];
    }
    if (tid < 32) {
        float a = g1[tid] * rsqrtf(rv1[tid] + 1e-5f);
        a1s[tid] = a;
        k1s[tid] = (b1[tid] - rm1[tid]) * a + bt1[tid];
    }
    __syncthreads();

    int ox = tid & 31;
    int oy = blockIdx.x * 4 + (tid >> 5);
    int oz = blockIdx.y;
    int n  = blockIdx.z;

    float acc[32];
#pragma unroll
    for (int c = 0; c < 32; c++) acc[c] = 0.f;
    int cnt = 0;
    const float* xb = x + n * DDD;
    const int*   mb = mask0 + n * DDD;

    for (int kd = 0; kd < 3; kd++)
        for (int kh = 0; kh < 3; kh++) {
            int base = (2 * oz + kd) * DD + (2 * oy + kh) * D0 + 2 * ox;
#pragma unroll
            for (int kw = 0; kw < 3; kw++) {
                float v = xb[base + kw];
                cnt += mb[base + kw];
                const float* wq = &w1s[((kd * 3 + kh) * 3 + kw) * 32];
#pragma unroll
                for (int c = 0; c < 32; c++) acc[c] += v * wq[c];
            }
        }

    float m = (cnt > 0) ? 1.f : 0.f;
    g_m1[n * SSS + (oz * S + oy) * S + ox] = m;
    float* hp = &g_h1[n * (C2 * PVOL) + (oz + 1) * PSLAB + (oy + 1) * PROW + (ox + 1)];
#pragma unroll
    for (int c = 0; c < 32; c++)
        hp[c * PVOL] = fmaxf(acc[c] * a1s[c] + k1s[c], 0.f) * m;
}

// ---------------- build lists: block-aggregated atomics ----------------
__global__ void buildlist_kernel(const int* __restrict__ mask0) {
    __shared__ int lc[8], lb[8];
    int tid = threadIdx.x;
    int i = blockIdx.x * 256 + tid;
    if (tid < 8) lc[tid] = 0;
    __syncthreads();
    int cls = -1, myp = 0;
    if (i < NB * DDD && mask0[i]) {
        int r = i % DDD;
        int oz = r / DD;
        int r2 = r % DD;
        int oy = r2 / D0;
        int ox = r2 % D0;
        cls = ((oz & 1) << 2) | ((oy & 1) << 1) | (ox & 1);
        myp = atomicAdd(&lc[cls], 1);
    }
    __syncthreads();
    if (tid < 8 && lc[tid] > 0) lb[tid] = atomicAdd(&g_cnt[tid], lc[tid]);
    __syncthreads();
    if (cls >= 0) {
        int slot = cls * LIST_STRIDE + lb[cls] + myp;
        g_list[slot] = i;
    }
}

// ---------------- conv2: halo-padded h1, NO bounds checks; co-half blocks ----------
// block 256 threads: xh = tid&15, cq = (tid>>4)&1, yy = tid>>5
// grid = (8, 32, 2): blockIdx.x = (oyBase<<1)|ch ; dyn smem = 27*32*16 floats (55.3 KB)
__global__ __launch_bounds__(256) void conv2_kernel() {
    extern __shared__ float w2s[];   // [tap][ci][co 16 for this half]
    int tid = threadIdx.x;
    int ch = blockIdx.x & 1;
    {
        const float4* src = (const float4*)g_W2T;
        float4* dst = (float4*)w2s;
        for (int i = tid; i < 27 * 32 * 4; i += 256) {
            int tc = i >> 2, j = i & 3;
            dst[tc * 4 + j] = src[tc * 8 + ch * 4 + j];
        }
    }
    __syncthreads();

    int xh = tid & 15;               // site pair ox0 = 2*xh, ox1 = 2*xh+1
    int cq = (tid >> 4) & 1;         // quarter within half: 8 co
    int oy = (blockIdx.x >> 1) * 8 + (tid >> 5);
    int oz = blockIdx.y;
    int n  = blockIdx.z;
    int cob = cq * 8;                // offset within the 16-wide smem slab
    int cobase = ch * 16 + cob;      // global co base (8 channels)

    unsigned long long accA[4], accB[4];   // 4 co-pairs per site
#pragma unroll
    for (int i = 0; i < 4; i++) { accA[i] = 0ull; accB[i] = 0ull; }

    // padded base: h index (oz+kd, oy+kh, 2*xh) covers zs=oz+kd-1 etc. with halo
    const float* hbase = g_h1 + n * (C2 * PVOL) + oz * PSLAB + oy * PROW + 2 * xh;

#pragma unroll
    for (int kd = 0; kd < 3; kd++) {
#pragma unroll
        for (int kh = 0; kh < 3; kh++) {
            const float* rowp = hbase + kd * PSLAB + kh * PROW;
            int tap0 = (kd * 3 + kh) * 3;
            const float* wt0 = &w2s[(tap0 + 0) * 512 + cob];
            const float* wt1 = &w2s[(tap0 + 1) * 512 + cob];
            const float* wt2 = &w2s[(tap0 + 2) * 512 + cob];
#pragma unroll 4
            for (int ci = 0; ci < 32; ci++) {
                const float* rp = rowp + ci * PVOL;
                float h0 = rp[0];
                float h1v = rp[1];
                float h2v = rp[2];
                float h3 = rp[3];
                unsigned long long hh0 = pack2(h0);
                unsigned long long hh1 = pack2(h1v);
                unsigned long long hh2 = pack2(h2v);
                unsigned long long hh3 = pack2(h3);
                const ulonglong2* wq0 = (const ulonglong2*)(wt0 + ci * 16);
                const ulonglong2* wq1 = (const ulonglong2*)(wt1 + ci * 16);
                const ulonglong2* wq2 = (const ulonglong2*)(wt2 + ci * 16);
#pragma unroll
                for (int q = 0; q < 2; q++) {
                    ulonglong2 w0 = wq0[q];
                    ulonglong2 w1 = wq1[q];
                    ulonglong2 w2 = wq2[q];
                    // site0 uses h[j=kw], site1 uses h[j=kw+1]
                    ffma2(accA[2 * q],     w0.x, hh0);
                    ffma2(accA[2 * q + 1], w0.y, hh0);
                    ffma2(accB[2 * q],     w0.x, hh1);
                    ffma2(accB[2 * q + 1], w0.y, hh1);
                    ffma2(accA[2 * q],     w1.x, hh1);
                    ffma2(accA[2 * q + 1], w1.y, hh1);
                    ffma2(accB[2 * q],     w1.x, hh2);
                    ffma2(accB[2 * q + 1], w1.y, hh2);
                    ffma2(accA[2 * q],     w2.x, hh2);
                    ffma2(accA[2 * q + 1], w2.y, hh2);
                    ffma2(accB[2 * q],     w2.x, hh3);
                    ffma2(accB[2 * q + 1], w2.y, hh3);
                }
            }
        }
    }

    int loc0 = (oz * S + oy) * S + 2 * xh;
    float m0 = g_m1[n * SSS + loc0];
    float m1v = g_m1[n * SSS + loc0 + 1];
    float* op0 = &g_h2[(n * SSS + loc0) * 32 + cobase];
    float* op1 = op0 + 32;
#pragma unroll
    for (int j = 0; j < 4; j++) {
        float2 va = unpack2(accA[j]);
        float2 vb = unpack2(accB[j]);
        int c0 = cobase + 2 * j, c1 = c0 + 1;
        float a0 = g_a2[c0], a1 = g_a2[c1], k0 = g_k2[c0], k1 = g_k2[c1];
        op0[2 * j]     = fmaxf(va.x * a0 + k0, 0.f) * m0;
        op0[2 * j + 1] = fmaxf(va.y * a1 + k1, 0.f) * m0;
        op1[2 * j]     = fmaxf(vb.x * a0 + k0, 0.f) * m1v;
        op1[2 * j + 1] = fmaxf(vb.y * a1 + k1, 0.f) * m1v;
    }
}

// ---------------- zero-fill output ----------------
__global__ void zero_kernel(float4* __restrict__ out4, int n4, float* __restrict__ out, int rem_start, int total) {
    int i = blockIdx.x * blockDim.x + threadIdx.x;
    if (i < n4) out4[i] = make_float4(0.f, 0.f, 0.f, 0.f);
    if (i == 0) {
        for (int j = rem_start; j < total; j++) out[j] = 0.f;
    }
}

// ---------------- inverse (transposed stride-2) conv at active sites, f32x2 ----------
// grid = (256, 8): blockIdx.y = parity class; 128 threads (co = tid)
__global__ __launch_bounds__(128) void invconv_kernel(const float* __restrict__ binv,
                                                      float* __restrict__ out) {
    int cls = blockIdx.y;
    int count = g_cnt[cls];
    int base = blockIdx.x * G;
    if (base >= count) return;

    int pz = (cls >> 2) & 1, py = (cls >> 1) & 1, px = cls & 1;
    int ndz = pz ? 1 : 2, ndy = py ? 1 : 2, ndx = px ? 1 : 2;
    int numT = ndz * ndy * ndx;

    __shared__ float h2s[8 * 32 * 36];   // [t][ci][pad36] g fastest
    __shared__ int   sbase[G * 8];
    __shared__ int   kmap[8];
    __shared__ int   ssite[G];
    __shared__ int   sout[G];

    int tid = threadIdx.x;
    int ng = count - base;
    if (ng > G) ng = G;

    if (tid < ng) {
        int s = g_list[cls * LIST_STRIDE + base + tid];
        ssite[tid] = s;
        sout[tid] = s + ((s >= DDD) ? 99 * DDD : 0);   // n*CO*DDD + r (co added later)
    }
    if (tid < numT) {
        int t = tid;
        int tz = t / (ndy * ndx), ty = (t / ndx) % ndy, tx = t % ndx;
        int kd = pz ? 1 : tz * 2, kh = py ? 1 : ty * 2, kw = px ? 1 : tx * 2;
        kmap[t] = (kd * 3 + kh) * 3 + kw;
    }
    __syncthreads();

    for (int i = tid; i < ng * numT; i += 128) {
        int g = i / numT, t = i % numT;
        int s = ssite[g];
        int n = s / DDD;
        int r = s % DDD;
        int oz = r / DD;
        int r2 = r % DD;
        int oy = r2 / D0;
        int ox = r2 % D0;
        int tz = t / (ndy * ndx), ty = (t / ndx) % ndy, tx = t % ndx;
        int kd = pz ? 1 : tz * 2, kh = py ? 1 : ty * 2, kw = px ? 1 : tx * 2;
        int iz = (oz + kd - 2) >> 1;
        int iy = (oy + kh - 2) >> 1;
        int ix = (ox + kw - 2) >> 1;
        bool v = ((unsigned)iz < 32u) && ((unsigned)iy < 32u) && ((unsigned)ix < 32u);
        sbase[g * 8 + t] = v ? ((((n * S + iz) * S + iy) * S + ix) * 32) : -1;
    }
    __syncthreads();

    // cooperative load of h2 tap rows (source ci-coalesced, dest [t][ci][g])
    for (int i = tid; i < G * numT * 32; i += 128) {
        int ci = i & 31;
        int gt = i >> 5;
        int g = gt / numT, t = gt % numT;
        int b = (g < ng) ? sbase[g * 8 + t] : -1;
        h2s[(t * 32 + ci) * 36 + g] = (b >= 0) ? g_h2[b + ci] : 0.f;
    }
    __syncthreads();

    int co = tid;
    bool cok = (co < CO);
    float bv = cok ? __ldg(&binv[co]) : 0.f;
    unsigned long long acc2[16];
    unsigned long long bb = pack2(bv);
#pragma unroll
    for (int j = 0; j < 16; j++) acc2[j] = bb;

    for (int t = 0; t < numT; t++) {
        const float* wp = g_WT + kmap[t] * 3200 + co;
        const float* hb = &h2s[(t * 32) * 36];
#pragma unroll 4
        for (int ci = 0; ci < 32; ci++) {
            float w = cok ? __ldg(wp + ci * 100) : 0.f;
            unsigned long long ww = pack2(w);
            const ulonglong2* hq = (const ulonglong2*)(hb + ci * 36);
#pragma unroll
            for (int q = 0; q < 8; q++) {
                ulonglong2 hv = hq[q];
                ffma2(acc2[2 * q],     ww, hv.x);
                ffma2(acc2[2 * q + 1], ww, hv.y);
            }
        }
    }

    if (cok) {
        int cd = co * DDD;
#pragma unroll
        for (int j = 0; j < 16; j++) {
            float2 v = unpack2(acc2[j]);
            int g0 = 2 * j, g1 = 2 * j + 1;
            if (g0 < ng) out[sout[g0] + cd] = v.x;
            if (g1 < ng) out[sout[g1] + cd] = v.y;
        }
    }
}

// ---------------- launch ----------------
extern "C" void kernel_launch(void* const* d_in, const int* in_sizes, int n_in,
                              void* d_out, int out_size) {
    const float* x    = (const float*)d_in[0];
    const int*   mask0 = (const int*)d_in[1];
    const float* W1   = (const float*)d_in[2];
    const float* b1   = (const float*)d_in[3];
    const float* g1   = (const float*)d_in[4];
    const float* bt1  = (const float*)d_in[5];
    const float* rm1  = (const float*)d_in[6];
    const float* rv1  = (const float*)d_in[7];
    const float* W2   = (const float*)d_in[8];
    const float* b2   = (const float*)d_in[9];
    const float* g2   = (const float*)d_in[10];
    const float* bt2  = (const float*)d_in[11];
    const float* rm2  = (const float*)d_in[12];
    const float* rv2  = (const float*)d_in[13];
    const float* Winv = (const float*)d_in[14];
    const float* binv = (const float*)d_in[15];
    float* out = (float*)d_out;

    cudaFuncSetAttribute(conv2_kernel, cudaFuncAttributeMaxDynamicSharedMemorySize,
                         27 * 32 * 16 * (int)sizeof(float));

    prep_kernel<<<512, 256>>>(W2, Winv, b2, g2, bt2, rm2, rv2);
    conv1_kernel<<<dim3(8, 32, 2), 128>>>(x, mask0, W1, b1, g1, bt1, rm1, rv1);
    buildlist_kernel<<<(NB * DDD + 255) / 256, 256>>>(mask0);
    conv2_kernel<<<dim3(8, 32, 2), 256, 27 * 32 * 16 * sizeof(float)>>>();

    int n4 = out_size >> 2;
    zero_kernel<<<(n4 + 255) / 256, 256>>>((float4*)d_out, n4, out, n4 << 2, out_size);

    invconv_kernel<<<dim3(256, 8), 128>>>(binv, out);
}

// round 13
// speedup vs baseline: 1.0783x; 1.0183x over previous
#include <cuda_runtime.h>

// ---------------- constants ----------------
#define D0 65
#define DD 4225          // 65*65
#define DDD 274625       // 65*65*65
#define S 32
#define SSS 32768        // 32^3
#define NB 2
#define C2 32
#define CO 100
#define G 32             // sites per block in invconv
#define LIST_STRIDE 72000
// padded h1 dims (1-voxel zero halo)
#define PROW 34          // x stride = 1, y stride = 34
#define PSLAB 1156       // 34*34
#define PVOL 39304       // 34*34*34

// ---------------- static scratch ----------------
__device__ float g_h1[NB*C2*PVOL];  // PLANAR PADDED [n][c][z+1][y+1][x+1]; halo stays 0
__device__ float g_h2[NB*SSS*C2];   // channels-last [n][z][y][x][c]
__device__ float g_m1[NB*SSS];
__device__ float g_W2T[27*32*32];   // [tap][ci][co]
__device__ float g_WT[27*32*100];   // [tap][ci][co]
__device__ float g_a2[32], g_k2[32];
__device__ int   g_list[8*LIST_STRIDE];
__device__ int   g_cnt[8];

// ---------------- f32x2 helpers ----------------
__device__ __forceinline__ void ffma2(unsigned long long &d, unsigned long long a, unsigned long long b) {
    asm("fma.rn.f32x2 %0, %1, %2, %0;" : "+l"(d) : "l"(a), "l"(b));
}
__device__ __forceinline__ unsigned long long pack2(float x) {
    unsigned long long r;
    asm("mov.b64 %0, {%1, %1};" : "=l"(r) : "f"(x));
    return r;
}
__device__ __forceinline__ float2 unpack2(unsigned long long v) {
    float2 r;
    asm("mov.b64 {%0, %1}, %2;" : "=f"(r.x), "=f"(r.y) : "l"(v));
    return r;
}

// ---------------- prep: fold BN2, transpose weights, reset counters ----------------
__global__ void prep_kernel(const float* __restrict__ W2, const float* __restrict__ Winv,
                            const float* __restrict__ b2, const float* __restrict__ g2,
                            const float* __restrict__ bt2, const float* __restrict__ rm2,
                            const float* __restrict__ rv2) {
    int tid = blockIdx.x * blockDim.x + threadIdx.x;
    int nth = gridDim.x * blockDim.x;
    if (tid < 8) g_cnt[tid] = 0;
    if (tid < 32) {
        float a2 = g2[tid] * rsqrtf(rv2[tid] + 1e-5f);
        g_a2[tid] = a2;
        g_k2[tid] = (b2[tid] - rm2[tid]) * a2 + bt2[tid];
    }
    for (int i = tid; i < 27 * 32 * 32; i += nth) {
        int k = i / 1024, r = i % 1024, ci = r / 32, co = r % 32;
        g_W2T[i] = W2[(co * 32 + ci) * 27 + k];
    }
    for (int i = tid; i < 27 * 32 * 100; i += nth) {
        int k = i / 3200, r = i % 3200, ci = r / 100, co = r % 100;
        g_WT[i] = Winv[(co * 32 + ci) * 27 + k];
    }
}

// ---------------- conv1 + BN + ReLU + mask (writes PADDED planar h1) ----------------
__global__ void conv1_kernel(const float* __restrict__ x, const int* __restrict__ mask0,
                             const float* __restrict__ W1,
                             const float* __restrict__ b1, const float* __restrict__ g1,
                             const float* __restrict__ bt1, const float* __restrict__ rm1,
                             const float* __restrict__ rv1) {
    __shared__ float w1s[27 * 32];
    __shared__ float a1s[32], k1s[32];
    int tid = threadIdx.x;
    for (int i = tid; i < 864; i += 128) {
        int k = i >> 5, c = i & 31;
        w1s[i] = W1[c * 27 + k];
    }
    if (tid < 32) {
        float a = g1[tid] * rsqrtf(rv1[tid] + 1e-5f);
        a1s[tid] = a;
        k1s[tid] = (b1[tid] - rm1[tid]) * a + bt1[tid];
    }
    __syncthreads();

    int ox = tid & 31;
    int oy = blockIdx.x * 4 + (tid >> 5);
    int oz = blockIdx.y;
    int n  = blockIdx.z;

    float acc[32];
#pragma unroll
    for (int c = 0; c < 32; c++) acc[c] = 0.f;
    int cnt = 0;
    const float* xb = x + n * DDD;
    const int*   mb = mask0 + n * DDD;

    for (int kd = 0; kd < 3; kd++)
        for (int kh = 0; kh < 3; kh++) {
            int base = (2 * oz + kd) * DD + (2 * oy + kh) * D0 + 2 * ox;
#pragma unroll
            for (int kw = 0; kw < 3; kw++) {
                float v = xb[base + kw];
                cnt += mb[base + kw];
                const float* wq = &w1s[((kd * 3 + kh) * 3 + kw) * 32];
#pragma unroll
                for (int c = 0; c < 32; c++) acc[c] += v * wq[c];
            }
        }

    float m = (cnt > 0) ? 1.f : 0.f;
    g_m1[n * SSS + (oz * S + oy) * S + ox] = m;
    float* hp = &g_h1[n * (C2 * PVOL) + (oz + 1) * PSLAB + (oy + 1) * PROW + (ox + 1)];
#pragma unroll
    for (int c = 0; c < 32; c++)
        hp[c * PVOL] = fmaxf(acc[c] * a1s[c] + k1s[c], 0.f) * m;
}

// ---------------- build lists: block-aggregated atomics ----------------
__global__ void buildlist_kernel(const int* __restrict__ mask0) {
    __shared__ int lc[8], lb[8];
    int tid = threadIdx.x;
    int i = blockIdx.x * 256 + tid;
    if (tid < 8) lc[tid] = 0;
    __syncthreads();
    int cls = -1, myp = 0;
    if (i < NB * DDD && mask0[i]) {
        int r = i % DDD;
        int oz = r / DD;
        int r2 = r % DD;
        int oy = r2 / D0;
        int ox = r2 % D0;
        cls = ((oz & 1) << 2) | ((oy & 1) << 1) | (ox & 1);
        myp = atomicAdd(&lc[cls], 1);
    }
    __syncthreads();
    if (tid < 8 && lc[tid] > 0) lb[tid] = atomicAdd(&g_cnt[tid], lc[tid]);
    __syncthreads();
    if (cls >= 0) {
        int slot = cls * LIST_STRIDE + lb[cls] + myp;
        g_list[slot] = i;
    }
}

// ---------------- conv2: halo-padded h1, float2 h loads; co-half blocks ----------
// block 256 threads: xh = tid&15, cq = (tid>>4)&1, yy = tid>>5
// grid = (8, 32, 2): blockIdx.x = (oyBase<<1)|ch ; dyn smem = 27*32*16 floats (55.3 KB)
__global__ __launch_bounds__(256) void conv2_kernel() {
    extern __shared__ float w2s[];   // [tap][ci][co 16 for this half]
    int tid = threadIdx.x;
    int ch = blockIdx.x & 1;
    {
        const float4* src = (const float4*)g_W2T;
        float4* dst = (float4*)w2s;
        for (int i = tid; i < 27 * 32 * 4; i += 256) {
            int tc = i >> 2, j = i & 3;
            dst[tc * 4 + j] = src[tc * 8 + ch * 4 + j];
        }
    }
    __syncthreads();

    int xh = tid & 15;               // site pair ox0 = 2*xh, ox1 = 2*xh+1
    int cq = (tid >> 4) & 1;         // quarter within half: 8 co
    int oy = (blockIdx.x >> 1) * 8 + (tid >> 5);
    int oz = blockIdx.y;
    int n  = blockIdx.z;
    int cob = cq * 8;                // offset within the 16-wide smem slab
    int cobase = ch * 16 + cob;      // global co base (8 channels)

    unsigned long long accA[4], accB[4];   // 4 co-pairs per site
#pragma unroll
    for (int i = 0; i < 4; i++) { accA[i] = 0ull; accB[i] = 0ull; }

    // padded base: h index (oz+kd, oy+kh, 2*xh) covers zs=oz+kd-1 etc. with halo
    const float* hbase = g_h1 + n * (C2 * PVOL) + oz * PSLAB + oy * PROW + 2 * xh;

#pragma unroll
    for (int kd = 0; kd < 3; kd++) {
#pragma unroll
        for (int kh = 0; kh < 3; kh++) {
            const float* rowp = hbase + kd * PSLAB + kh * PROW;
            int tap0 = (kd * 3 + kh) * 3;
            const float* wt0 = &w2s[(tap0 + 0) * 512 + cob];
            const float* wt1 = &w2s[(tap0 + 1) * 512 + cob];
            const float* wt2 = &w2s[(tap0 + 2) * 512 + cob];
#pragma unroll 4
            for (int ci = 0; ci < 32; ci++) {
                const float2* rp2 = (const float2*)(rowp + ci * PVOL);  // 8B aligned
                float2 p01 = rp2[0];
                float2 p23 = rp2[1];
                unsigned long long hh0 = pack2(p01.x);
                unsigned long long hh1 = pack2(p01.y);
                unsigned long long hh2 = pack2(p23.x);
                unsigned long long hh3 = pack2(p23.y);
                const ulonglong2* wq0 = (const ulonglong2*)(wt0 + ci * 16);
                const ulonglong2* wq1 = (const ulonglong2*)(wt1 + ci * 16);
                const ulonglong2* wq2 = (const ulonglong2*)(wt2 + ci * 16);
#pragma unroll
                for (int q = 0; q < 2; q++) {
                    ulonglong2 w0 = wq0[q];
                    ulonglong2 w1 = wq1[q];
                    ulonglong2 w2 = wq2[q];
                    // site0 uses h[j=kw], site1 uses h[j=kw+1]
                    ffma2(accA[2 * q],     w0.x, hh0);
                    ffma2(accA[2 * q + 1], w0.y, hh0);
                    ffma2(accB[2 * q],     w0.x, hh1);
                    ffma2(accB[2 * q + 1], w0.y, hh1);
                    ffma2(accA[2 * q],     w1.x, hh1);
                    ffma2(accA[2 * q + 1], w1.y, hh1);
                    ffma2(accB[2 * q],     w1.x, hh2);
                    ffma2(accB[2 * q + 1], w1.y, hh2);
                    ffma2(accA[2 * q],     w2.x, hh2);
                    ffma2(accA[2 * q + 1], w2.y, hh2);
                    ffma2(accB[2 * q],     w2.x, hh3);
                    ffma2(accB[2 * q + 1], w2.y, hh3);
                }
            }
        }
    }

    int loc0 = (oz * S + oy) * S + 2 * xh;
    float m0 = g_m1[n * SSS + loc0];
    float m1v = g_m1[n * SSS + loc0 + 1];
    float* op0 = &g_h2[(n * SSS + loc0) * 32 + cobase];
    float* op1 = op0 + 32;
#pragma unroll
    for (int j = 0; j < 4; j++) {
        float2 va = unpack2(accA[j]);
        float2 vb = unpack2(accB[j]);
        int c0 = cobase + 2 * j, c1 = c0 + 1;
        float a0 = g_a2[c0], a1 = g_a2[c1], k0 = g_k2[c0], k1 = g_k2[c1];
        op0[2 * j]     = fmaxf(va.x * a0 + k0, 0.f) * m0;
        op0[2 * j + 1] = fmaxf(va.y * a1 + k1, 0.f) * m0;
        op1[2 * j]     = fmaxf(vb.x * a0 + k0, 0.f) * m1v;
        op1[2 * j + 1] = fmaxf(vb.y * a1 + k1, 0.f) * m1v;
    }
}

// ---------------- zero-fill output ----------------
__global__ void zero_kernel(float4* __restrict__ out4, int n4, float* __restrict__ out, int rem_start, int total) {
    int i = blockIdx.x * blockDim.x + threadIdx.x;
    if (i < n4) out4[i] = make_float4(0.f, 0.f, 0.f, 0.f);
    if (i == 0) {
        for (int j = rem_start; j < total; j++) out[j] = 0.f;
    }
}

// ---------------- inverse (transposed stride-2) conv at active sites, f32x2 ----------
// grid = (256, 8): blockIdx.y = parity class; 128 threads (co = tid)
__global__ __launch_bounds__(128) void invconv_kernel(const float* __restrict__ binv,
                                                      float* __restrict__ out) {
    int cls = blockIdx.y;
    int count = g_cnt[cls];
    int base = blockIdx.x * G;
    if (base >= count) return;

    int pz = (cls >> 2) & 1, py = (cls >> 1) & 1, px = cls & 1;
    int ndz = pz ? 1 : 2, ndy = py ? 1 : 2, ndx = px ? 1 : 2;
    int numT = ndz * ndy * ndx;

    __shared__ float h2s[8 * 32 * 36];   // [t][ci][pad36] g fastest
    __shared__ int   sbase[G * 8];
    __shared__ int   kmap[8];
    __shared__ int   ssite[G];
    __shared__ int   sout[G];

    int tid = threadIdx.x;
    int ng = count - base;
    if (ng > G) ng = G;

    if (tid < ng) {
        int s = g_list[cls * LIST_STRIDE + base + tid];
        ssite[tid] = s;
        sout[tid] = s + ((s >= DDD) ? 99 * DDD : 0);   // n*CO*DDD + r (co added later)
    }
    if (tid < numT) {
        int t = tid;
        int tz = t / (ndy * ndx), ty = (t / ndx) % ndy, tx = t % ndx;
        int kd = pz ? 1 : tz * 2, kh = py ? 1 : ty * 2, kw = px ? 1 : tx * 2;
        kmap[t] = (kd * 3 + kh) * 3 + kw;
    }
    __syncthreads();

    for (int i = tid; i < ng * numT; i += 128) {
        int g = i / numT, t = i % numT;
        int s = ssite[g];
        int n = s / DDD;
        int r = s % DDD;
        int oz = r / DD;
        int r2 = r % DD;
        int oy = r2 / D0;
        int ox = r2 % D0;
        int tz = t / (ndy * ndx), ty = (t / ndx) % ndy, tx = t % ndx;
        int kd = pz ? 1 : tz * 2, kh = py ? 1 : ty * 2, kw = px ? 1 : tx * 2;
        int iz = (oz + kd - 2) >> 1;
        int iy = (oy + kh - 2) >> 1;
        int ix = (ox + kw - 2) >> 1;
        bool v = ((unsigned)iz < 32u) && ((unsigned)iy < 32u) && ((unsigned)ix < 32u);
        sbase[g * 8 + t] = v ? ((((n * S + iz) * S + iy) * S + ix) * 32) : -1;
    }
    __syncthreads();

    // cooperative load of h2 tap rows (source ci-coalesced, dest [t][ci][g])
    for (int i = tid; i < G * numT * 32; i += 128) {
        int ci = i & 31;
        int gt = i >> 5;
        int g = gt / numT, t = gt % numT;
        int b = (g < ng) ? sbase[g * 8 + t] : -1;
        h2s[(t * 32 + ci) * 36 + g] = (b >= 0) ? g_h2[b + ci] : 0.f;
    }
    __syncthreads();

    int co = tid;
    bool cok = (co < CO);
    float bv = cok ? __ldg(&binv[co]) : 0.f;
    unsigned long long acc2[16];
    unsigned long long bb = pack2(bv);
#pragma unroll
    for (int j = 0; j < 16; j++) acc2[j] = bb;

    for (int t = 0; t < numT; t++) {
        const float* wp = g_WT + kmap[t] * 3200 + co;
        const float* hb = &h2s[(t * 32) * 36];
#pragma unroll 4
        for (int ci = 0; ci < 32; ci++) {
            float w = cok ? __ldg(wp + ci * 100) : 0.f;
            unsigned long long ww = pack2(w);
            const ulonglong2* hq = (const ulonglong2*)(hb + ci * 36);
#pragma unroll
            for (int q = 0; q < 8; q++) {
                ulonglong2 hv = hq[q];
                ffma2(acc2[2 * q],     ww, hv.x);
                ffma2(acc2[2 * q + 1], ww, hv.y);
            }
        }
    }

    if (cok) {
        int cd = co * DDD;
#pragma unroll
        for (int j = 0; j < 16; j++) {
            float2 v = unpack2(acc2[j]);
            int g0 = 2 * j, g1 = 2 * j + 1;
            if (g0 < ng) out[sout[g0] + cd] = v.x;
            if (g1 < ng) out[sout[g1] + cd] = v.y;
        }
    }
}

// ---------------- launch ----------------
extern "C" void kernel_launch(void* const* d_in, const int* in_sizes, int n_in,
                              void* d_out, int out_size) {
    const float* x    = (const float*)d_in[0];
    const int*   mask0 = (const int*)d_in[1];
    const float* W1   = (const float*)d_in[2];
    const float* b1   = (const float*)d_in[3];
    const float* g1   = (const float*)d_in[4];
    const float* bt1  = (const float*)d_in[5];
    const float* rm1  = (const float*)d_in[6];
    const float* rv1  = (const float*)d_in[7];
    const float* W2   = (const float*)d_in[8];
    const float* b2   = (const float*)d_in[9];
    const float* g2   = (const float*)d_in[10];
    const float* bt2  = (const float*)d_in[11];
    const float* rm2  = (const float*)d_in[12];
    const float* rv2  = (const float*)d_in[13];
    const float* Winv = (const float*)d_in[14];
    const float* binv = (const float*)d_in[15];
    float* out = (float*)d_out;

    cudaFuncSetAttribute(conv2_kernel, cudaFuncAttributeMaxDynamicSharedMemorySize,
                         27 * 32 * 16 * (int)sizeof(float));

    prep_kernel<<<512, 256>>>(W2, Winv, b2, g2, bt2, rm2, rv2);
    conv1_kernel<<<dim3(8, 32, 2), 128>>>(x, mask0, W1, b1, g1, bt1, rm1, rv1);
    buildlist_kernel<<<(NB * DDD + 255) / 256, 256>>>(mask0);
    conv2_kernel<<<dim3(8, 32, 2), 256, 27 * 32 * 16 * sizeof(float)>>>();

    int n4 = out_size >> 2;
    zero_kernel<<<(n4 + 255) / 256, 256>>>((float4*)d_out, n4, out, n4 << 2, out_size);

    invconv_kernel<<<dim3(256, 8), 128>>>(binv, out);
}

// round 14
// speedup vs baseline: 1.2171x; 1.1287x over previous
#include <cuda_runtime.h>

// ---------------- constants ----------------
#define D0 65
#define DD 4225          // 65*65
#define DDD 274625       // 65*65*65
#define S 32
#define SSS 32768        // 32^3
#define NB 2
#define C2 32
#define CO 100
#define G 32             // sites per block in invconv
#define LIST_STRIDE 72000
// padded h1 dims (1-voxel zero halo)
#define PROW 34          // x stride = 1, y stride = 34
#define PSLAB 1156       // 34*34
#define PVOL 39304       // 34*34*34
// fused grids
#define CONV1_BLOCKS 256
#define BL_BLOCKS 2146       // ceil(NB*DDD/256)
#define CONV2_BLOCKS 512

// ---------------- static scratch ----------------
__device__ float g_h1[NB*C2*PVOL];  // PLANAR PADDED [n][c][z+1][y+1][x+1]; halo stays 0
__device__ float g_h2[NB*SSS*C2];   // channels-last [n][z][y][x][c]
__device__ float g_m1[NB*SSS];
__device__ float g_W2T[27*32*32];   // [tap][ci][co]
__device__ float g_WT[27*32*100];   // [tap][ci][co]
__device__ float g_a2[32], g_k2[32];
__device__ int   g_list[8*LIST_STRIDE];
__device__ int   g_cnt[8];

// ---------------- f32x2 helpers ----------------
__device__ __forceinline__ void ffma2(unsigned long long &d, unsigned long long a, unsigned long long b) {
    asm("fma.rn.f32x2 %0, %1, %2, %0;" : "+l"(d) : "l"(a), "l"(b));
}
__device__ __forceinline__ unsigned long long pack2(float x) {
    unsigned long long r;
    asm("mov.b64 %0, {%1, %1};" : "=l"(r) : "f"(x));
    return r;
}
__device__ __forceinline__ float2 unpack2(unsigned long long v) {
    float2 r;
    asm("mov.b64 {%0, %1}, %2;" : "=f"(r.x), "=f"(r.y) : "l"(v));
    return r;
}

// ---------------- prep: fold BN2, transpose weights, reset counters ----------------
__global__ void prep_kernel(const float* __restrict__ W2, const float* __restrict__ Winv,
                            const float* __restrict__ b2, const float* __restrict__ g2,
                            const float* __restrict__ bt2, const float* __restrict__ rm2,
                            const float* __restrict__ rv2) {
    int tid = blockIdx.x * blockDim.x + threadIdx.x;
    int nth = gridDim.x * blockDim.x;
    if (tid < 8) g_cnt[tid] = 0;
    if (tid < 32) {
        float a2 = g2[tid] * rsqrtf(rv2[tid] + 1e-5f);
        g_a2[tid] = a2;
        g_k2[tid] = (b2[tid] - rm2[tid]) * a2 + bt2[tid];
    }
    for (int i = tid; i < 27 * 32 * 32; i += nth) {
        int k = i / 1024, r = i % 1024, ci = r / 32, co = r % 32;
        g_W2T[i] = W2[(co * 32 + ci) * 27 + k];
    }
    for (int i = tid; i < 27 * 32 * 100; i += nth) {
        int k = i / 3200, r = i % 3200, ci = r / 100, co = r % 100;
        g_WT[i] = Winv[(co * 32 + ci) * 27 + k];
    }
}

// ---------------- FUSED conv1 + buildlist (both depend only on prep) --------------
// 1D grid, 256 threads. blocks [0,CONV1_BLOCKS): conv1 (8 oy rows each);
// blocks [CONV1_BLOCKS, +BL_BLOCKS): buildlist.
__global__ __launch_bounds__(256) void conv1_aux_kernel(
        const float* __restrict__ x, const int* __restrict__ mask0,
        const float* __restrict__ W1,
        const float* __restrict__ b1, const float* __restrict__ g1,
        const float* __restrict__ bt1, const float* __restrict__ rm1,
        const float* __restrict__ rv1) {
    int b = blockIdx.x;
    int tid = threadIdx.x;

    if (b >= CONV1_BLOCKS) {
        // ---- buildlist branch ----
        __shared__ int lc[8], lb[8];
        int i = (b - CONV1_BLOCKS) * 256 + tid;
        if (tid < 8) lc[tid] = 0;
        __syncthreads();
        int cls = -1, myp = 0;
        if (i < NB * DDD && mask0[i]) {
            int r = i % DDD;
            int oz = r / DD;
            int r2 = r % DD;
            int oy = r2 / D0;
            int ox = r2 % D0;
            cls = ((oz & 1) << 2) | ((oy & 1) << 1) | (ox & 1);
            myp = atomicAdd(&lc[cls], 1);
        }
        __syncthreads();
        if (tid < 8 && lc[tid] > 0) lb[tid] = atomicAdd(&g_cnt[tid], lc[tid]);
        __syncthreads();
        if (cls >= 0) g_list[cls * LIST_STRIDE + lb[cls] + myp] = i;
        return;
    }

    // ---- conv1 branch: block = (bx, oz, n) flattened; 256 thr = 32x * 8oy ----
    __shared__ float w1s[27 * 32];
    __shared__ float a1s[32], k1s[32];
    for (int i = tid; i < 864; i += 256) {
        int k = i >> 5, c = i & 31;
        w1s[i] = W1[c * 27 + k];
    }
    if (tid < 32) {
        float a = g1[tid] * rsqrtf(rv1[tid] + 1e-5f);
        a1s[tid] = a;
        k1s[tid] = (b1[tid] - rm1[tid]) * a + bt1[tid];
    }
    __syncthreads();

    int bx = b & 3;                  // 4 oy groups
    int oz = (b >> 2) & 31;
    int n  = b >> 7;
    int ox = tid & 31;
    int oy = bx * 8 + (tid >> 5);

    float acc[32];
#pragma unroll
    for (int c = 0; c < 32; c++) acc[c] = 0.f;
    int cnt = 0;
    const float* xb = x + n * DDD;
    const int*   mb = mask0 + n * DDD;

    for (int kd = 0; kd < 3; kd++)
        for (int kh = 0; kh < 3; kh++) {
            int base = (2 * oz + kd) * DD + (2 * oy + kh) * D0 + 2 * ox;
#pragma unroll
            for (int kw = 0; kw < 3; kw++) {
                float v = xb[base + kw];
                cnt += mb[base + kw];
                const float* wq = &w1s[((kd * 3 + kh) * 3 + kw) * 32];
#pragma unroll
                for (int c = 0; c < 32; c++) acc[c] += v * wq[c];
            }
        }

    float m = (cnt > 0) ? 1.f : 0.f;
    g_m1[n * SSS + (oz * S + oy) * S + ox] = m;
    float* hp = &g_h1[n * (C2 * PVOL) + (oz + 1) * PSLAB + (oy + 1) * PROW + (ox + 1)];
#pragma unroll
    for (int c = 0; c < 32; c++)
        hp[c * PVOL] = fmaxf(acc[c] * a1s[c] + k1s[c], 0.f) * m;
}

// ---------------- FUSED conv2 + zero-fill ----------------------------------------
// 1D grid, 256 threads. blocks [0,CONV2_BLOCKS): conv2 (halo-padded, co-half);
// blocks beyond: float4 zero-fill of out (overlaps DRAM with conv2 compute).
__global__ __launch_bounds__(256) void conv2_zero_kernel(float* __restrict__ out, int out_size) {
    int b = blockIdx.x;
    int tid = threadIdx.x;

    if (b >= CONV2_BLOCKS) {
        // ---- zero branch ----
        int zb = b - CONV2_BLOCKS;
        int n4 = out_size >> 2;
        float4* o4 = (float4*)out;
        float4 z = make_float4(0.f, 0.f, 0.f, 0.f);
        int base = zb * 1024 + tid;
#pragma unroll
        for (int k = 0; k < 4; k++) {
            int idx = base + k * 256;
            if (idx < n4) o4[idx] = z;
        }
        if (zb == 0 && tid == 0)
            for (int j = n4 << 2; j < out_size; j++) out[j] = 0.f;
        return;
    }

    // ---- conv2 branch ----
    extern __shared__ float w2s[];   // [tap][ci][co 16 for this half]
    int ch = b & 1;
    {
        const float4* src = (const float4*)g_W2T;
        float4* dst = (float4*)w2s;
        for (int i = tid; i < 27 * 32 * 4; i += 256) {
            int tc = i >> 2, j = i & 3;
            dst[tc * 4 + j] = src[tc * 8 + ch * 4 + j];
        }
    }
    __syncthreads();

    int xh = tid & 15;               // site pair ox0 = 2*xh, ox1 = 2*xh+1
    int cq = (tid >> 4) & 1;         // quarter within half: 8 co
    int oy = ((b >> 1) & 3) * 8 + (tid >> 5);
    int oz = (b >> 3) & 31;
    int n  = b >> 8;
    int cob = cq * 8;                // offset within the 16-wide smem slab
    int cobase = ch * 16 + cob;      // global co base (8 channels)

    unsigned long long accA[4], accB[4];   // 4 co-pairs per site
#pragma unroll
    for (int i = 0; i < 4; i++) { accA[i] = 0ull; accB[i] = 0ull; }

    const float* hbase = g_h1 + n * (C2 * PVOL) + oz * PSLAB + oy * PROW + 2 * xh;

#pragma unroll
    for (int kd = 0; kd < 3; kd++) {
#pragma unroll
        for (int kh = 0; kh < 3; kh++) {
            const float* rowp = hbase + kd * PSLAB + kh * PROW;
            int tap0 = (kd * 3 + kh) * 3;
            const float* wt0 = &w2s[(tap0 + 0) * 512 + cob];
            const float* wt1 = &w2s[(tap0 + 1) * 512 + cob];
            const float* wt2 = &w2s[(tap0 + 2) * 512 + cob];
#pragma unroll 4
            for (int ci = 0; ci < 32; ci++) {
                const float2* rp2 = (const float2*)(rowp + ci * PVOL);  // 8B aligned
                float2 p01 = rp2[0];
                float2 p23 = rp2[1];
                unsigned long long hh0 = pack2(p01.x);
                unsigned long long hh1 = pack2(p01.y);
                unsigned long long hh2 = pack2(p23.x);
                unsigned long long hh3 = pack2(p23.y);
                const ulonglong2* wq0 = (const ulonglong2*)(wt0 + ci * 16);
                const ulonglong2* wq1 = (const ulonglong2*)(wt1 + ci * 16);
                const ulonglong2* wq2 = (const ulonglong2*)(wt2 + ci * 16);
#pragma unroll
                for (int q = 0; q < 2; q++) {
                    ulonglong2 w0 = wq0[q];
                    ulonglong2 w1 = wq1[q];
                    ulonglong2 w2 = wq2[q];
                    ffma2(accA[2 * q],     w0.x, hh0);
                    ffma2(accA[2 * q + 1], w0.y, hh0);
                    ffma2(accB[2 * q],     w0.x, hh1);
                    ffma2(accB[2 * q + 1], w0.y, hh1);
                    ffma2(accA[2 * q],     w1.x, hh1);
                    ffma2(accA[2 * q + 1], w1.y, hh1);
                    ffma2(accB[2 * q],     w1.x, hh2);
                    ffma2(accB[2 * q + 1], w1.y, hh2);
                    ffma2(accA[2 * q],     w2.x, hh2);
                    ffma2(accA[2 * q + 1], w2.y, hh2);
                    ffma2(accB[2 * q],     w2.x, hh3);
                    ffma2(accB[2 * q + 1], w2.y, hh3);
                }
            }
        }
    }

    int loc0 = (oz * S + oy) * S + 2 * xh;
    float m0 = g_m1[n * SSS + loc0];
    float m1v = g_m1[n * SSS + loc0 + 1];
    float* op0 = &g_h2[(n * SSS + loc0) * 32 + cobase];
    float* op1 = op0 + 32;
#pragma unroll
    for (int j = 0; j < 4; j++) {
        float2 va = unpack2(accA[j]);
        float2 vb = unpack2(accB[j]);
        int c0 = cobase + 2 * j, c1 = c0 + 1;
        float a0 = g_a2[c0], a1 = g_a2[c1], k0 = g_k2[c0], k1 = g_k2[c1];
        op0[2 * j]     = fmaxf(va.x * a0 + k0, 0.f) * m0;
        op0[2 * j + 1] = fmaxf(va.y * a1 + k1, 0.f) * m0;
        op1[2 * j]     = fmaxf(vb.x * a0 + k0, 0.f) * m1v;
        op1[2 * j + 1] = fmaxf(vb.y * a1 + k1, 0.f) * m1v;
    }
}

// ---------------- inverse (transposed stride-2) conv at active sites, f32x2 ----------
// grid = (256, 8): blockIdx.y = parity class; 128 threads (co = tid)
__global__ __launch_bounds__(128) void invconv_kernel(const float* __restrict__ binv,
                                                      float* __restrict__ out) {
    int cls = blockIdx.y;
    int count = g_cnt[cls];
    int base = blockIdx.x * G;
    if (base >= count) return;

    int pz = (cls >> 2) & 1, py = (cls >> 1) & 1, px = cls & 1;
    int ndz = pz ? 1 : 2, ndy = py ? 1 : 2, ndx = px ? 1 : 2;
    int numT = ndz * ndy * ndx;

    __shared__ float h2s[8 * 32 * 36];   // [t][ci][pad36] g fastest
    __shared__ int   sbase[G * 8];
    __shared__ int   kmap[8];
    __shared__ int   ssite[G];
    __shared__ int   sout[G];

    int tid = threadIdx.x;
    int ng = count - base;
    if (ng > G) ng = G;

    if (tid < ng) {
        int s = g_list[cls * LIST_STRIDE + base + tid];
        ssite[tid] = s;
        sout[tid] = s + ((s >= DDD) ? 99 * DDD : 0);   // n*CO*DDD + r (co added later)
    }
    if (tid < numT) {
        int t = tid;
        int tz = t / (ndy * ndx), ty = (t / ndx) % ndy, tx = t % ndx;
        int kd = pz ? 1 : tz * 2, kh = py ? 1 : ty * 2, kw = px ? 1 : tx * 2;
        kmap[t] = (kd * 3 + kh) * 3 + kw;
    }
    __syncthreads();

    for (int i = tid; i < ng * numT; i += 128) {
        int g = i / numT, t = i % numT;
        int s = ssite[g];
        int n = s / DDD;
        int r = s % DDD;
        int oz = r / DD;
        int r2 = r % DD;
        int oy = r2 / D0;
        int ox = r2 % D0;
        int tz = t / (ndy * ndx), ty = (t / ndx) % ndy, tx = t % ndx;
        int kd = pz ? 1 : tz * 2, kh = py ? 1 : ty * 2, kw = px ? 1 : tx * 2;
        int iz = (oz + kd - 2) >> 1;
        int iy = (oy + kh - 2) >> 1;
        int ix = (ox + kw - 2) >> 1;
        bool v = ((unsigned)iz < 32u) && ((unsigned)iy < 32u) && ((unsigned)ix < 32u);
        sbase[g * 8 + t] = v ? ((((n * S + iz) * S + iy) * S + ix) * 32) : -1;
    }
    __syncthreads();

    // cooperative load of h2 tap rows (source ci-coalesced, dest [t][ci][g])
    for (int i = tid; i < G * numT * 32; i += 128) {
        int ci = i & 31;
        int gt = i >> 5;
        int g = gt / numT, t = gt % numT;
        int b = (g < ng) ? sbase[g * 8 + t] : -1;
        h2s[(t * 32 + ci) * 36 + g] = (b >= 0) ? g_h2[b + ci] : 0.f;
    }
    __syncthreads();

    int co = tid;
    bool cok = (co < CO);
    float bv = cok ? __ldg(&binv[co]) : 0.f;
    unsigned long long acc2[16];
    unsigned long long bb = pack2(bv);
#pragma unroll
    for (int j = 0; j < 16; j++) acc2[j] = bb;

    for (int t = 0; t < numT; t++) {
        const float* wp = g_WT + kmap[t] * 3200 + co;
        const float* hb = &h2s[(t * 32) * 36];
#pragma unroll 4
        for (int ci = 0; ci < 32; ci++) {
            float w = cok ? __ldg(wp + ci * 100) : 0.f;
            unsigned long long ww = pack2(w);
            const ulonglong2* hq = (const ulonglong2*)(hb + ci * 36);
#pragma unroll
            for (int q = 0; q < 8; q++) {
                ulonglong2 hv = hq[q];
                ffma2(acc2[2 * q],     ww, hv.x);
                ffma2(acc2[2 * q + 1], ww, hv.y);
            }
        }
    }

    if (cok) {
        int cd = co * DDD;
#pragma unroll
        for (int j = 0; j < 16; j++) {
            float2 v = unpack2(acc2[j]);
            int g0 = 2 * j, g1 = 2 * j + 1;
            if (g0 < ng) out[sout[g0] + cd] = v.x;
            if (g1 < ng) out[sout[g1] + cd] = v.y;
        }
    }
}

// ---------------- launch ----------------
extern "C" void kernel_launch(void* const* d_in, const int* in_sizes, int n_in,
                              void* d_out, int out_size) {
    const float* x    = (const float*)d_in[0];
    const int*   mask0 = (const int*)d_in[1];
    const float* W1   = (const float*)d_in[2];
    const float* b1   = (const float*)d_in[3];
    const float* g1   = (const float*)d_in[4];
    const float* bt1  = (const float*)d_in[5];
    const float* rm1  = (const float*)d_in[6];
    const float* rv1  = (const float*)d_in[7];
    const float* W2   = (const float*)d_in[8];
    const float* b2   = (const float*)d_in[9];
    const float* g2   = (const float*)d_in[10];
    const float* bt2  = (const float*)d_in[11];
    const float* rm2  = (const float*)d_in[12];
    const float* rv2  = (const float*)d_in[13];
    const float* Winv = (const float*)d_in[14];
    const float* binv = (const float*)d_in[15];
    float* out = (float*)d_out;

    cudaFuncSetAttribute(conv2_zero_kernel, cudaFuncAttributeMaxDynamicSharedMemorySize,
                         27 * 32 * 16 * (int)sizeof(float));

    prep_kernel<<<512, 256>>>(W2, Winv, b2, g2, bt2, rm2, rv2);
    conv1_aux_kernel<<<CONV1_BLOCKS + BL_BLOCKS, 256>>>(x, mask0, W1, b1, g1, bt1, rm1, rv1);

    int n4 = out_size >> 2;
    int zblocks = (n4 + 1023) / 1024;
    conv2_zero_kernel<<<CONV2_BLOCKS + zblocks, 256, 27 * 32 * 16 * sizeof(float)>>>(out, out_size);

    invconv_kernel<<<dim3(256, 8), 128>>>(binv, out);
}